// round 10
// baseline (speedup 1.0000x reference)
#include <cuda_runtime.h>
#include <cuda_bf16.h>
#include <cstdint>

// DotAttentionEluX — math collapses:
//   attn[i,j] = ks_j / sum_j ks_j  (query cancels in row normalization)
//   out[b,h,i,:] = (sum_j ks_j * v_j) / (sum_j ks_j)   -- same for every row i
// with ks_j = sum_d (elu(k[b,h,j,d]) + 1).
//
// Evidence: read phase ~5us (near DRAM roof); write of 16MB pins at ~7us /
// ~2.3TB/s across STG, TMA, and hybrid (R9) -> shared write-ingress cap.
// R7/R8 single-kernel fusions regressed (reader degradation). R10: keep both
// proven kernels intact and overlap them with Programmatic Dependent Launch.
// Writer CTAs spin on per-bh counters and start writing a bh the moment its
// 16 reader CTAs have posted partials.

static constexpr int B_ = 4, H_ = 8, L_ = 2048, D_ = 64;
static constexpr int BH = B_ * H_;                  // 32
static constexpr int NSPLIT = 16;
static constexpr int ROWS_PER_SPLIT = L_ / NSPLIT;  // 128
static constexpr int WARPS = 8;

__device__ float g_num[BH * NSPLIT * D_];
__device__ float g_den[BH * NSPLIT];
__device__ int   g_cnt[BH];       // reader arrives per bh (0..16)
__device__ int   g_consumed[BH];  // writer consumption; 8th resets both

__device__ __forceinline__ float elu1(float x) {
    return x > 0.0f ? x + 1.0f : __expf(x);
}

// ---------------- accum: proven R6 reader + arrive/trigger ----------------
__global__ __launch_bounds__(256) void accum_kernel(
    const float* __restrict__ K, const float* __restrict__ V)
{
#if __CUDA_ARCH__ >= 900
    cudaTriggerProgrammaticLaunchCompletion();   // let writer kernel launch
#endif
    const int blk   = blockIdx.x;       // 0..511
    const int bh    = blk / NSPLIT;
    const int split = blk % NSPLIT;
    const int warp  = threadIdx.x >> 5;
    const int lane  = threadIdx.x & 31;
    const int half  = lane >> 4;
    const int q     = lane & 15;

    const int row0 = split * ROWS_PER_SPLIT;
    const size_t base = ((size_t)bh * L_ + row0 + (size_t)warp * 2 + half) * D_
                        + (size_t)q * 4;
    const float4* __restrict__ Kp = reinterpret_cast<const float4*>(K + base);
    const float4* __restrict__ Vp = reinterpret_cast<const float4*>(V + base);
    constexpr int STRIDE4 = WARPS * 2 * D_ / 4;
    constexpr int NPAIR   = ROWS_PER_SPLIT / (WARPS * 2);   // 8

    float n0 = 0.f, n1 = 0.f, n2 = 0.f, n3 = 0.f, den = 0.f;

    #pragma unroll
    for (int r = 0; r < NPAIR; r++) {
        float4 kk = Kp[(size_t)r * STRIDE4];
        float4 vv = Vp[(size_t)r * STRIDE4];
        float ks = elu1(kk.x) + elu1(kk.y) + elu1(kk.z) + elu1(kk.w);
        #pragma unroll
        for (int o = 8; o; o >>= 1)
            ks += __shfl_xor_sync(0xffffffffu, ks, o);
        n0 += ks * vv.x;  n1 += ks * vv.y;
        n2 += ks * vv.z;  n3 += ks * vv.w;
        if (q == 0) den += ks;
    }

    __shared__ float4 s_num[WARPS * 2][D_ / 4];
    __shared__ float  s_den[WARPS * 2];
    const int wh = warp * 2 + half;
    s_num[wh][q] = make_float4(n0, n1, n2, n3);
    if (q == 0) s_den[wh] = den;
    __syncthreads();

    const int t = threadIdx.x;
    if (t < D_) {
        const float* sn = reinterpret_cast<const float*>(s_num);
        float s = 0.0f;
        #pragma unroll
        for (int w = 0; w < WARPS * 2; w++) s += sn[w * D_ + t];
        g_num[(bh * NSPLIT + split) * D_ + t] = s;
    }
    if (t == D_) {
        float s = 0.0f;
        #pragma unroll
        for (int w = 0; w < WARPS * 2; w++) s += s_den[w];
        g_den[bh * NSPLIT + split] = s;
    }
    __syncthreads();                 // all partial stores issued
    if (t == 0) {
        __threadfence();             // release partials before arrive
        atomicAdd(&g_cnt[bh], 1);
    }
}

// ---------------- bcast: proven R9 TMA writer + per-bh spin ----------------
static constexpr int NWRITE = 256;                        // 8 writers per bh
static constexpr int SEG_ROWS = L_ / 8;                   // 256 rows each
static constexpr int STAGE_ROWS = 32;
static constexpr int STAGE_BYTES = STAGE_ROWS * D_ * 4;   // 8192

__global__ __launch_bounds__(256) void bcast_kernel(float* __restrict__ out)
{
    const int bh  = blockIdx.x >> 3;   // 0..31
    const int seg = blockIdx.x & 7;    // 0..7
    const int t   = threadIdx.x;

    __shared__ alignas(128) float4 s_buf[STAGE_ROWS * (D_ / 4)]; // 8 KB
    __shared__ float4 s_w4[D_ / 4];

    if (t == 0) {                       // wait for this bh's 16 partials
        volatile int* p = &g_cnt[bh];
        while (*p < NSPLIT) { __nanosleep(128); }
        __threadfence();                // acquire
    }
    __syncthreads();

    if (t < D_) {
        const float* __restrict__ pn = g_num + bh * NSPLIT * D_ + t;
        float num = 0.0f, den = 0.0f;
        #pragma unroll
        for (int sp = 0; sp < NSPLIT; sp++) {
            num += __ldcg(pn + sp * D_);
            den += __ldcg(&g_den[bh * NSPLIT + sp]);
        }
        reinterpret_cast<float*>(s_w4)[t] = num / den;
    }
    __syncthreads();

    {   // replicate the 256B row into 32 staged rows
        const float4 v = s_w4[t & 15];
        const int r0 = t >> 4;          // 0..15
        s_buf[r0 * (D_ / 4) + (t & 15)] = v;
        s_buf[(r0 + 16) * (D_ / 4) + (t & 15)] = v;
    }
    __syncthreads();

    if (t == 0) {
        asm volatile("fence.proxy.async.shared::cta;" ::: "memory");
        uint32_t saddr = (uint32_t)__cvta_generic_to_shared(s_buf);
        #pragma unroll
        for (int i = 0; i < SEG_ROWS / STAGE_ROWS; i++) {   // 8 x 8KB
            const float* gdst = out + ((size_t)bh * L_
                + (size_t)seg * SEG_ROWS + (size_t)i * STAGE_ROWS) * D_;
            asm volatile(
                "cp.async.bulk.global.shared::cta.bulk_group [%0], [%1], %2;"
                :: "l"(gdst), "r"(saddr), "r"((int)STAGE_BYTES) : "memory");
        }
        asm volatile("cp.async.bulk.commit_group;" ::: "memory");
        asm volatile("cp.async.bulk.wait_group.read 0;" ::: "memory");

        // 8th consumer of this bh resets counters for the next graph replay.
        int c = atomicAdd(&g_consumed[bh], 1);
        if (c == 7) { g_cnt[bh] = 0; g_consumed[bh] = 0; }
    }
}

extern "C" void kernel_launch(void* const* d_in, const int* in_sizes, int n_in,
                              void* d_out, int out_size)
{
    // metadata order: query, key, value. Query is mathematically irrelevant.
    const float* K = (const float*)d_in[1];
    const float* V = (const float*)d_in[2];
    float* out = (float*)d_out;

    accum_kernel<<<BH * NSPLIT, 256>>>(K, V);

    // Writer via Programmatic Dependent Launch: starts while accum runs,
    // synchronizes per-bh through g_cnt. Falls back to a plain launch if the
    // attribute is rejected (then g_cnt is already complete when it runs).
    cudaLaunchConfig_t cfg = {};
    cfg.gridDim  = dim3(NWRITE);
    cfg.blockDim = dim3(256);
    cfg.dynamicSmemBytes = 0;
    cfg.stream = 0;
    cudaLaunchAttribute attr[1];
    attr[0].id = cudaLaunchAttributeProgrammaticStreamSerialization;
    attr[0].val.programmaticStreamSerializationAllowed = 1;
    cfg.attrs = attr;
    cfg.numAttrs = 1;
    cudaError_t e = cudaLaunchKernelEx(&cfg, bcast_kernel, out);
    if (e != cudaSuccess) {
        bcast_kernel<<<NWRITE, 256>>>(out);
    }
}

// round 11
// speedup vs baseline: 1.2569x; 1.2569x over previous
#include <cuda_runtime.h>
#include <cuda_bf16.h>
#include <cstdint>

// DotAttentionEluX — math collapses:
//   out[b,h,i,:] = (sum_j ks_j * v_j) / (sum_j ks_j)  for every row i,
//   ks_j = sum_d (elu(k[b,h,j,d]) + 1).  Query cancels entirely.
//
// Evidence R4-R10: reads need a barrier-free MLP-16 loop (5.6TB/s @512 CTAs);
// 16MB write pins at ~2.3TB/s (7us) across STG/TMA/hybrid; PDL and global
// barriers regress. R11: ONE kernel, 256 reader CTAs do TWO R6-structured
// passes (bh 0-15 then bh 16-31) so half the output is ready at ~3.3us;
// 256 co-resident writer CTAs spin per-bh and pipeline writes (L2 ingress)
// behind the remaining reads (DRAM) — disjoint resources.

static constexpr int B_ = 4, H_ = 8, L_ = 2048, D_ = 64;
static constexpr int BH = B_ * H_;                  // 32
static constexpr int NSPLIT = 16;
static constexpr int ROWS_PER_SPLIT = L_ / NSPLIT;  // 128
static constexpr int WARPS = 8;
static constexpr int NREADER = 256;                 // 16 bh-groups x 16 splits
static constexpr int NWRITER = 256;                 // 8 writers per bh
static constexpr int NCTA = NREADER + NWRITER;      // 512, all co-resident

__device__ float g_num[BH * NSPLIT * D_];
__device__ float g_den[BH * NSPLIT];
__device__ int   g_cnt[BH];       // reader arrives (0..16) per bh
__device__ int   g_consumed[BH];  // writer completions; 8th resets both

__device__ __forceinline__ float elu1(float x) {
    return x > 0.0f ? x + 1.0f : __expf(x);
}

static constexpr int SEG_ROWS = L_ / 8;                   // 256 rows per writer
static constexpr int STAGE_ROWS = 32;
static constexpr int STAGE_BYTES = STAGE_ROWS * D_ * 4;   // 8192

struct SmemReader { float4 s_num[WARPS * 2][D_ / 4]; float s_den[WARPS * 2]; };
struct SmemWriter { float4 s_buf[STAGE_ROWS * (D_ / 4)]; float4 s_w4[D_ / 4]; };

__global__ __launch_bounds__(256) void fused_kernel(
    const float* __restrict__ K, const float* __restrict__ V,
    float* __restrict__ out)
{
    __shared__ union U { SmemReader r; SmemWriter w;
                         __device__ U() {} } sm;
    const int t    = threadIdx.x;
    const int warp = t >> 5;
    const int lane = t & 31;
    const int half = lane >> 4;
    const int q    = lane & 15;

    if (blockIdx.x < NREADER) {
        // ------------------ READER: two staggered passes ------------------
        const int split = blockIdx.x & 15;
        const int grp   = blockIdx.x >> 4;      // 0..15

        #pragma unroll 1
        for (int p = 0; p < 2; p++) {
            const int bh = p * 16 + grp;
            // Proven R6 body: warp covers rows warp*2+half + 16*r, r<8.
            const size_t base = ((size_t)bh * L_ + split * ROWS_PER_SPLIT
                                 + (size_t)warp * 2 + half) * D_ + (size_t)q * 4;
            const float4* __restrict__ Kp = reinterpret_cast<const float4*>(K + base);
            const float4* __restrict__ Vp = reinterpret_cast<const float4*>(V + base);
            constexpr int STRIDE4 = WARPS * 2 * D_ / 4;          // 16 rows
            constexpr int NPAIR   = ROWS_PER_SPLIT / (WARPS * 2); // 8

            float n0 = 0.f, n1 = 0.f, n2 = 0.f, n3 = 0.f, den = 0.f;
            #pragma unroll
            for (int r = 0; r < NPAIR; r++) {
                float4 kk = Kp[(size_t)r * STRIDE4];
                float4 vv = Vp[(size_t)r * STRIDE4];
                float ks = elu1(kk.x) + elu1(kk.y) + elu1(kk.z) + elu1(kk.w);
                #pragma unroll
                for (int o = 8; o; o >>= 1)
                    ks += __shfl_xor_sync(0xffffffffu, ks, o);
                n0 += ks * vv.x;  n1 += ks * vv.y;
                n2 += ks * vv.z;  n3 += ks * vv.w;
                if (q == 0) den += ks;
            }

            const int wh = warp * 2 + half;
            sm.r.s_num[wh][q] = make_float4(n0, n1, n2, n3);
            if (q == 0) sm.r.s_den[wh] = den;
            __syncthreads();

            if (t < D_) {
                const float* sn = reinterpret_cast<const float*>(sm.r.s_num);
                float s = 0.0f;
                #pragma unroll
                for (int w = 0; w < WARPS * 2; w++) s += sn[w * D_ + t];
                g_num[(bh * NSPLIT + split) * D_ + t] = s;
            }
            if (t == D_) {
                float s = 0.0f;
                #pragma unroll
                for (int w = 0; w < WARPS * 2; w++) s += sm.r.s_den[w];
                g_den[bh * NSPLIT + split] = s;
            }
            // Release: every thread fences its own partial stores, then one
            // arrive. The barrier also guards smem reuse by the next pass.
            __threadfence();
            __syncthreads();
            if (t == 0) atomicAdd(&g_cnt[bh], 1);
        }
    } else {
        // ------------------ WRITER: per-bh spin + TMA bulk ----------------
        const int w   = blockIdx.x - NREADER;   // 0..255
        const int bh  = w >> 3;                 // 0..31
        const int seg = w & 7;                  // 0..7

        if (t == 0) {
            volatile int* p = &g_cnt[bh];
            while (*p < NSPLIT) { __nanosleep(128); }
            __threadfence();                    // acquire
        }
        __syncthreads();

        if (t < D_) {
            const float* __restrict__ pn = g_num + bh * NSPLIT * D_ + t;
            float num = 0.0f, den = 0.0f;
            #pragma unroll
            for (int sp = 0; sp < NSPLIT; sp++) {
                num += __ldcg(pn + sp * D_);
                den += __ldcg(&g_den[bh * NSPLIT + sp]);
            }
            reinterpret_cast<float*>(sm.w.s_w4)[t] = num / den;
        }
        __syncthreads();

        {   // replicate 256B row into 32 staged rows (2 STS.128 each)
            const float4 v = sm.w.s_w4[t & 15];
            const int r0 = t >> 4;              // 0..15
            sm.w.s_buf[r0 * (D_ / 4) + (t & 15)] = v;
            sm.w.s_buf[(r0 + 16) * (D_ / 4) + (t & 15)] = v;
        }
        __syncthreads();

        if (t == 0) {
            asm volatile("fence.proxy.async.shared::cta;" ::: "memory");
            uint32_t saddr = (uint32_t)__cvta_generic_to_shared(sm.w.s_buf);
            #pragma unroll
            for (int i = 0; i < SEG_ROWS / STAGE_ROWS; i++) {   // 8 x 8KB
                const float* gdst = out + ((size_t)bh * L_
                    + (size_t)seg * SEG_ROWS + (size_t)i * STAGE_ROWS) * D_;
                asm volatile(
                    "cp.async.bulk.global.shared::cta.bulk_group [%0], [%1], %2;"
                    :: "l"(gdst), "r"(saddr), "r"((int)STAGE_BYTES) : "memory");
            }
            asm volatile("cp.async.bulk.commit_group;" ::: "memory");
            asm volatile("cp.async.bulk.wait_group.read 0;" ::: "memory");

            // Last of 8 writers resets this bh's counters for the next replay.
            // Safe: every writer passed the spin before incrementing here.
            int c = atomicAdd(&g_consumed[bh], 1);
            if (c == 7) { g_cnt[bh] = 0; g_consumed[bh] = 0; }
        }
    }
}

extern "C" void kernel_launch(void* const* d_in, const int* in_sizes, int n_in,
                              void* d_out, int out_size)
{
    // metadata order: query, key, value. Query is mathematically irrelevant.
    const float* K = (const float*)d_in[1];
    const float* V = (const float*)d_in[2];
    float* out = (float*)d_out;

    fused_kernel<<<NCTA, 256>>>(K, V, out);
}